// round 15
// baseline (speedup 1.0000x reference)
#include <cuda_runtime.h>
#include <cstdint>

// Problem-fixed maxima (N=100000, E=3200000 per reference setup_inputs).
#define MAXN 100000
#define MAXE 3200000

// Scratch (allocation-free contract: __device__ globals).
// Note: zero-initialized at module load; k_prep restores g_cnt to 0 each call.
__device__ int g_cnt[MAXN];                        // in-degree (excluding self-loop)
__device__ __align__(16) float g_xs[MAXN * 4];     // x * dinv  (source-scaled payload)
__device__ __align__(16) float g_accx[MAXN * 4];   // layer-1 accumulator (pre dst-scale)
__device__ __align__(16) float g_t2s[MAXN * 4];    // t2 * dinv (source-scaled payload)
__device__ __align__(16) float g_acc2[MAXN * 4];   // layer-2 accumulator (pre dst-scale)
__device__ float g_dinv[MAXN];                     // rsqrt(deg)

__device__ __forceinline__ void red_add_v4(float* addr, float a, float b, float c, float d) {
    asm volatile("red.global.add.v4.f32 [%0], {%1, %2, %3, %4};"
                 :: "l"(addr), "f"(a), "f"(b), "f"(c), "f"(d) : "memory");
}

// 1) in-degree histogram, 8 edges/thread via 2x int4
__global__ void k_count(const int* __restrict__ edge_index, int E) {
    int i = blockIdx.x * blockDim.x + threadIdx.x;
    int e0 = i * 8;
    if (e0 >= E) return;
    const int* dstp = edge_index + E;
    if (e0 + 7 < E) {
        int4 a = *reinterpret_cast<const int4*>(dstp + e0);
        int4 b = *reinterpret_cast<const int4*>(dstp + e0 + 4);
        atomicAdd(&g_cnt[a.x], 1);
        atomicAdd(&g_cnt[a.y], 1);
        atomicAdd(&g_cnt[a.z], 1);
        atomicAdd(&g_cnt[a.w], 1);
        atomicAdd(&g_cnt[b.x], 1);
        atomicAdd(&g_cnt[b.y], 1);
        atomicAdd(&g_cnt[b.z], 1);
        atomicAdd(&g_cnt[b.w], 1);
    } else {
        for (int e = e0; e < E; e++) atomicAdd(&g_cnt[dstp[e]], 1);
    }
}

// 2) dinv = rsqrt(deg+1); payload xs = x * dinv; seed accx with payload (self-loop:
//    post-scale by dinv[d] later yields x[d] * dinv[d]^2). Resets g_cnt for next call.
__global__ void k_prep(const float* __restrict__ x, int n) {
    int i = blockIdx.x * blockDim.x + threadIdx.x;
    if (i >= n) return;
    int c = g_cnt[i];
    g_cnt[i] = 0;  // restore zero for the next kernel_launch invocation
    float di = rsqrtf((float)(c + 1));
    g_dinv[i] = di;
    float4 p = make_float4(x[i * 3 + 0] * di, x[i * 3 + 1] * di, x[i * 3 + 2] * di, 0.f);
    reinterpret_cast<float4*>(g_xs)[i] = p;
    reinterpret_cast<float4*>(g_accx)[i] = p;
}

// 3) layer-1 scatter: weightless copy-scatter, 8 edges/thread (front-batched MLP).
__global__ void k_scatter_x(const int* __restrict__ edge_index, int E) {
    int i = blockIdx.x * blockDim.x + threadIdx.x;
    int e0 = i * 8;
    if (e0 >= E) return;
    const int* srcp = edge_index;
    const int* dstp = edge_index + E;
    const float4* xs = reinterpret_cast<const float4*>(g_xs);
    if (e0 + 7 < E) {
        int4 sa = *reinterpret_cast<const int4*>(srcp + e0);
        int4 sb = *reinterpret_cast<const int4*>(srcp + e0 + 4);
        int4 da = *reinterpret_cast<const int4*>(dstp + e0);
        int4 db = *reinterpret_cast<const int4*>(dstp + e0 + 4);
        float4 v0 = xs[sa.x];
        float4 v1 = xs[sa.y];
        float4 v2 = xs[sa.z];
        float4 v3 = xs[sa.w];
        float4 v4 = xs[sb.x];
        float4 v5 = xs[sb.y];
        float4 v6 = xs[sb.z];
        float4 v7 = xs[sb.w];
        red_add_v4(&g_accx[da.x * 4], v0.x, v0.y, v0.z, 0.f);
        red_add_v4(&g_accx[da.y * 4], v1.x, v1.y, v1.z, 0.f);
        red_add_v4(&g_accx[da.z * 4], v2.x, v2.y, v2.z, 0.f);
        red_add_v4(&g_accx[da.w * 4], v3.x, v3.y, v3.z, 0.f);
        red_add_v4(&g_accx[db.x * 4], v4.x, v4.y, v4.z, 0.f);
        red_add_v4(&g_accx[db.y * 4], v5.x, v5.y, v5.z, 0.f);
        red_add_v4(&g_accx[db.z * 4], v6.x, v6.y, v6.z, 0.f);
        red_add_v4(&g_accx[db.w * 4], v7.x, v7.y, v7.z, 0.f);
    } else {
        for (int e = e0; e < E; e++) {
            float4 v = xs[srcp[e]];
            red_add_v4(&g_accx[dstp[e] * 4], v.x, v.y, v.z, 0.f);
        }
    }
}

// 4) fused: agg1 = accx * dinv (dst post-scale) -> h = relu(agg1 @ W1 + b1) -> t2 = h @ W2;
//    payload t2s = t2 * dinv; seed acc2 with t2s (self-loop).
__global__ void k_fused_transform(const float* __restrict__ W1, const float* __restrict__ b1,
                                  const float* __restrict__ W2, int n) {
    __shared__ float sW1[96];   // W1 [3, 32] row-major
    __shared__ float sb1[32];
    __shared__ float sW2[96];   // W2 [32, 3] row-major
    if (threadIdx.x < 96) sW1[threadIdx.x] = W1[threadIdx.x];
    if (threadIdx.x < 32) sb1[threadIdx.x] = b1[threadIdx.x];
    if (threadIdx.x >= 128 && threadIdx.x < 224) sW2[threadIdx.x - 128] = W2[threadIdx.x - 128];
    __syncthreads();
    int i = blockIdx.x * blockDim.x + threadIdx.x;
    if (i >= n) return;
    float di = g_dinv[i];
    float4 a = reinterpret_cast<const float4*>(g_accx)[i];
    a.x *= di; a.y *= di; a.z *= di;  // dst-side normalization of layer-1 aggregation
    float c0 = 0.f, c1 = 0.f, c2 = 0.f;
#pragma unroll
    for (int j = 0; j < 32; j++) {
        float h = fmaxf(a.x * sW1[j] + a.y * sW1[32 + j] + a.z * sW1[64 + j] + sb1[j], 0.f);
        c0 += h * sW2[j * 3 + 0];
        c1 += h * sW2[j * 3 + 1];
        c2 += h * sW2[j * 3 + 2];
    }
    float4 p = make_float4(c0 * di, c1 * di, c2 * di, 0.f);  // source-scaled payload
    reinterpret_cast<float4*>(g_t2s)[i] = p;
    reinterpret_cast<float4*>(g_acc2)[i] = p;                 // self-loop seed
}

// 5) layer-2 scatter: weightless copy-scatter, 8 edges/thread.
__global__ void k_scatter2(const int* __restrict__ edge_index, int E) {
    int i = blockIdx.x * blockDim.x + threadIdx.x;
    int e0 = i * 8;
    if (e0 >= E) return;
    const int* srcp = edge_index;
    const int* dstp = edge_index + E;
    const float4* ts = reinterpret_cast<const float4*>(g_t2s);
    if (e0 + 7 < E) {
        int4 sa = *reinterpret_cast<const int4*>(srcp + e0);
        int4 sb = *reinterpret_cast<const int4*>(srcp + e0 + 4);
        int4 da = *reinterpret_cast<const int4*>(dstp + e0);
        int4 db = *reinterpret_cast<const int4*>(dstp + e0 + 4);
        float4 v0 = ts[sa.x];
        float4 v1 = ts[sa.y];
        float4 v2 = ts[sa.z];
        float4 v3 = ts[sa.w];
        float4 v4 = ts[sb.x];
        float4 v5 = ts[sb.y];
        float4 v6 = ts[sb.z];
        float4 v7 = ts[sb.w];
        red_add_v4(&g_acc2[da.x * 4], v0.x, v0.y, v0.z, 0.f);
        red_add_v4(&g_acc2[da.y * 4], v1.x, v1.y, v1.z, 0.f);
        red_add_v4(&g_acc2[da.z * 4], v2.x, v2.y, v2.z, 0.f);
        red_add_v4(&g_acc2[da.w * 4], v3.x, v3.y, v3.z, 0.f);
        red_add_v4(&g_acc2[db.x * 4], v4.x, v4.y, v4.z, 0.f);
        red_add_v4(&g_acc2[db.y * 4], v5.x, v5.y, v5.z, 0.f);
        red_add_v4(&g_acc2[db.z * 4], v6.x, v6.y, v6.z, 0.f);
        red_add_v4(&g_acc2[db.w * 4], v7.x, v7.y, v7.z, 0.f);
    } else {
        for (int e = e0; e < E; e++) {
            float4 v = ts[srcp[e]];
            red_add_v4(&g_acc2[dstp[e] * 4], v.x, v.y, v.z, 0.f);
        }
    }
}

// 6) out[i, :] = acc2[i, 0:3] * dinv[i] + b2 (dst post-scale + bias)
__global__ void k_out(const float* __restrict__ b2, float* __restrict__ out, int n) {
    int i = blockIdx.x * blockDim.x + threadIdx.x;
    if (i >= n) return;
    float di = g_dinv[i];
    float4 a = reinterpret_cast<const float4*>(g_acc2)[i];
    out[i * 3 + 0] = a.x * di + __ldg(&b2[0]);
    out[i * 3 + 1] = a.y * di + __ldg(&b2[1]);
    out[i * 3 + 2] = a.z * di + __ldg(&b2[2]);
}

extern "C" void kernel_launch(void* const* d_in, const int* in_sizes, int n_in,
                              void* d_out, int out_size) {
    const float* x = (const float*)d_in[0];
    const int* edge_index = (const int*)d_in[1];  // int32 (JAX x64 disabled)
    const float* W1 = (const float*)d_in[2];
    const float* b1 = (const float*)d_in[3];
    const float* W2 = (const float*)d_in[4];
    const float* b2 = (const float*)d_in[5];
    float* out = (float*)d_out;

    int n = in_sizes[0] / 3;
    int E = in_sizes[1] / 2;

    const int B = 256;
    int tE8 = ((E + 7) / 8 + B - 1) / B;
    int tN = (n + B - 1) / B;

    k_count<<<tE8, B>>>(edge_index, E);
    k_prep<<<tN, B>>>(x, n);
    k_scatter_x<<<tE8, B>>>(edge_index, E);
    k_fused_transform<<<tN, B>>>(W1, b1, W2, n);
    k_scatter2<<<tE8, B>>>(edge_index, E);
    k_out<<<tN, B>>>(b2, out, n);
}

// round 16
// speedup vs baseline: 1.0712x; 1.0712x over previous
#include <cuda_runtime.h>
#include <cstdint>

// Problem-fixed maxima (N=100000, E=3200000 per reference setup_inputs).
#define MAXN 100000
#define MAXE 3200000

// Scratch (allocation-free contract: __device__ globals).
// Note: zero-initialized at module load; k_prep restores g_cnt to 0 each call.
__device__ int g_cnt[MAXN];                        // in-degree (excluding self-loop)
__device__ __align__(16) float g_xs[MAXN * 4];     // x * dinv  (source-scaled payload)
__device__ __align__(16) float g_accx[MAXN * 4];   // layer-1 accumulator (pre dst-scale)
__device__ __align__(16) float g_t2s[MAXN * 4];    // t2 * dinv (source-scaled payload)
__device__ __align__(16) float g_acc2[MAXN * 4];   // layer-2 accumulator (pre dst-scale)
__device__ float g_dinv[MAXN];                     // rsqrt(deg)

__device__ __forceinline__ void red_add_v4(float* addr, float a, float b, float c, float d) {
    asm volatile("red.global.add.v4.f32 [%0], {%1, %2, %3, %4};"
                 :: "l"(addr), "f"(a), "f"(b), "f"(c), "f"(d) : "memory");
}

// 1) in-degree histogram, 4 edges/thread via int4
__global__ void k_count(const int* __restrict__ edge_index, int E) {
    int i = blockIdx.x * blockDim.x + threadIdx.x;
    int e0 = i * 4;
    if (e0 >= E) return;
    const int* dstp = edge_index + E;
    if (e0 + 3 < E) {
        int4 d4 = *reinterpret_cast<const int4*>(dstp + e0);
        atomicAdd(&g_cnt[d4.x], 1);
        atomicAdd(&g_cnt[d4.y], 1);
        atomicAdd(&g_cnt[d4.z], 1);
        atomicAdd(&g_cnt[d4.w], 1);
    } else {
        for (int e = e0; e < E; e++) atomicAdd(&g_cnt[dstp[e]], 1);
    }
}

// 2) dinv = rsqrt(deg+1); payload xs = x * dinv; seed accx with payload (self-loop:
//    post-scale by dinv[d] later yields x[d] * dinv[d]^2). Resets g_cnt for next call.
__global__ void k_prep(const float* __restrict__ x, int n) {
    int i = blockIdx.x * blockDim.x + threadIdx.x;
    if (i >= n) return;
    int c = g_cnt[i];
    g_cnt[i] = 0;  // restore zero for the next kernel_launch invocation
    float di = rsqrtf((float)(c + 1));
    g_dinv[i] = di;
    float4 p = make_float4(x[i * 3 + 0] * di, x[i * 3 + 1] * di, x[i * 3 + 2] * di, 0.f);
    reinterpret_cast<float4*>(g_xs)[i] = p;
    reinterpret_cast<float4*>(g_accx)[i] = p;
}

// 3) layer-1 scatter: weightless copy-scatter, 4 edges/thread (front-batched MLP).
__global__ void k_scatter_x(const int* __restrict__ edge_index, int E) {
    int i = blockIdx.x * blockDim.x + threadIdx.x;
    int e0 = i * 4;
    if (e0 >= E) return;
    const int* srcp = edge_index;
    const int* dstp = edge_index + E;
    const float4* xs = reinterpret_cast<const float4*>(g_xs);
    if (e0 + 3 < E) {
        int4 s4 = *reinterpret_cast<const int4*>(srcp + e0);
        int4 d4 = *reinterpret_cast<const int4*>(dstp + e0);
        float4 v0 = xs[s4.x];
        float4 v1 = xs[s4.y];
        float4 v2 = xs[s4.z];
        float4 v3 = xs[s4.w];
        red_add_v4(&g_accx[d4.x * 4], v0.x, v0.y, v0.z, 0.f);
        red_add_v4(&g_accx[d4.y * 4], v1.x, v1.y, v1.z, 0.f);
        red_add_v4(&g_accx[d4.z * 4], v2.x, v2.y, v2.z, 0.f);
        red_add_v4(&g_accx[d4.w * 4], v3.x, v3.y, v3.z, 0.f);
    } else {
        for (int e = e0; e < E; e++) {
            float4 v = xs[srcp[e]];
            red_add_v4(&g_accx[dstp[e] * 4], v.x, v.y, v.z, 0.f);
        }
    }
}

// 4) fused: agg1 = accx * dinv (dst post-scale) -> h = relu(agg1 @ W1 + b1) -> t2 = h @ W2;
//    payload t2s = t2 * dinv; seed acc2 with t2s (self-loop).
__global__ void k_fused_transform(const float* __restrict__ W1, const float* __restrict__ b1,
                                  const float* __restrict__ W2, int n) {
    __shared__ float sW1[96];   // W1 [3, 32] row-major
    __shared__ float sb1[32];
    __shared__ float sW2[96];   // W2 [32, 3] row-major
    if (threadIdx.x < 96) sW1[threadIdx.x] = W1[threadIdx.x];
    if (threadIdx.x < 32) sb1[threadIdx.x] = b1[threadIdx.x];
    if (threadIdx.x >= 128 && threadIdx.x < 224) sW2[threadIdx.x - 128] = W2[threadIdx.x - 128];
    __syncthreads();
    int i = blockIdx.x * blockDim.x + threadIdx.x;
    if (i >= n) return;
    float di = g_dinv[i];
    float4 a = reinterpret_cast<const float4*>(g_accx)[i];
    a.x *= di; a.y *= di; a.z *= di;  // dst-side normalization of layer-1 aggregation
    float c0 = 0.f, c1 = 0.f, c2 = 0.f;
#pragma unroll
    for (int j = 0; j < 32; j++) {
        float h = fmaxf(a.x * sW1[j] + a.y * sW1[32 + j] + a.z * sW1[64 + j] + sb1[j], 0.f);
        c0 += h * sW2[j * 3 + 0];
        c1 += h * sW2[j * 3 + 1];
        c2 += h * sW2[j * 3 + 2];
    }
    float4 p = make_float4(c0 * di, c1 * di, c2 * di, 0.f);  // source-scaled payload
    reinterpret_cast<float4*>(g_t2s)[i] = p;
    reinterpret_cast<float4*>(g_acc2)[i] = p;                 // self-loop seed
}

// 5) layer-2 scatter: weightless copy-scatter, 4 edges/thread.
__global__ void k_scatter2(const int* __restrict__ edge_index, int E) {
    int i = blockIdx.x * blockDim.x + threadIdx.x;
    int e0 = i * 4;
    if (e0 >= E) return;
    const int* srcp = edge_index;
    const int* dstp = edge_index + E;
    const float4* ts = reinterpret_cast<const float4*>(g_t2s);
    if (e0 + 3 < E) {
        int4 s4 = *reinterpret_cast<const int4*>(srcp + e0);
        int4 d4 = *reinterpret_cast<const int4*>(dstp + e0);
        float4 v0 = ts[s4.x];
        float4 v1 = ts[s4.y];
        float4 v2 = ts[s4.z];
        float4 v3 = ts[s4.w];
        red_add_v4(&g_acc2[d4.x * 4], v0.x, v0.y, v0.z, 0.f);
        red_add_v4(&g_acc2[d4.y * 4], v1.x, v1.y, v1.z, 0.f);
        red_add_v4(&g_acc2[d4.z * 4], v2.x, v2.y, v2.z, 0.f);
        red_add_v4(&g_acc2[d4.w * 4], v3.x, v3.y, v3.z, 0.f);
    } else {
        for (int e = e0; e < E; e++) {
            float4 v = ts[srcp[e]];
            red_add_v4(&g_acc2[dstp[e] * 4], v.x, v.y, v.z, 0.f);
        }
    }
}

// 6) out[i, :] = acc2[i, 0:3] * dinv[i] + b2 (dst post-scale + bias)
__global__ void k_out(const float* __restrict__ b2, float* __restrict__ out, int n) {
    int i = blockIdx.x * blockDim.x + threadIdx.x;
    if (i >= n) return;
    float di = g_dinv[i];
    float4 a = reinterpret_cast<const float4*>(g_acc2)[i];
    out[i * 3 + 0] = a.x * di + __ldg(&b2[0]);
    out[i * 3 + 1] = a.y * di + __ldg(&b2[1]);
    out[i * 3 + 2] = a.z * di + __ldg(&b2[2]);
}

extern "C" void kernel_launch(void* const* d_in, const int* in_sizes, int n_in,
                              void* d_out, int out_size) {
    const float* x = (const float*)d_in[0];
    const int* edge_index = (const int*)d_in[1];  // int32 (JAX x64 disabled)
    const float* W1 = (const float*)d_in[2];
    const float* b1 = (const float*)d_in[3];
    const float* W2 = (const float*)d_in[4];
    const float* b2 = (const float*)d_in[5];
    float* out = (float*)d_out;

    int n = in_sizes[0] / 3;
    int E = in_sizes[1] / 2;

    const int B = 256;
    int tE4 = ((E + 3) / 4 + B - 1) / B;
    int tN = (n + B - 1) / B;

    k_count<<<tE4, B>>>(edge_index, E);
    k_prep<<<tN, B>>>(x, n);
    k_scatter_x<<<tE4, B>>>(edge_index, E);
    k_fused_transform<<<tN, B>>>(W1, b1, W2, n);
    k_scatter2<<<tE4, B>>>(edge_index, E);
    k_out<<<tN, B>>>(b2, out, n);
}